// round 14
// baseline (speedup 1.0000x reference)
#include <cuda_runtime.h>
#include <cuda_fp16.h>
#include <cstdint>

namespace {

constexpr int ATOM = 128;
constexpr int BOND = 64;
constexpr int KTOT = 192;    // 48 float4 per row
constexpr int NOUT = 256;
constexpr int BM   = 128;    // edges per tile
constexpr int NTHREADS = 512;
constexpr int STRIDE = 100;  // row stride (words); %32=4 -> conflict-free frag LDS

// smem layout (4B words): B first, then two A buffers
constexpr int SM_B_W  = 0;                        // 256 x 100
constexpr int SM_A0_W = NOUT * STRIDE;            // 128 x 100
constexpr int SM_A1_W = SM_A0_W + BM * STRIDE;
constexpr int SMEM_BYTES = (SM_A1_W + BM * STRIDE) * 4;   // 204800

__device__ __forceinline__ uint32_t h2(float lo, float hi) {
    __half2 h = __floats2half2_rn(lo, hi);
    return *(uint32_t*)&h;
}

__global__ void __launch_bounds__(NTHREADS, 1)
bond_msg_kernel(const float* __restrict__ V,
                const float* __restrict__ E,
                const int* __restrict__ src0,      // edge_index row 0 (int32)
                const float* __restrict__ W,       // [NOUT, KTOT]
                const float* __restrict__ bias,    // [NOUT]
                float* __restrict__ out,           // [M, NOUT]
                int M, int ntiles)
{
    extern __shared__ uint32_t smem[];
    uint32_t* Bs = smem + SM_B_W;
    uint32_t* Abuf[2] = { smem + SM_A0_W, smem + SM_A1_W };

    const int tid  = threadIdx.x;
    const int lane = tid & 31;
    const int wid  = tid >> 5;
    const int warp_m = wid >> 2;   // 0..3 -> quarter-group; 32 A rows each
    const int warp_n = wid & 3;    // 0..3 (64 cols each)
    const int lr = lane >> 2;
    const int lc = lane & 3;
    const int gtid = tid & 127;    // tid within the 128-thread quarter-group
    const int G  = gridDim.x;

    // ---- Loop-invariant bias fragments (R10 reloaded these every tile).
    float2 bias_v[8];
    #pragma unroll
    for (int ni = 0; ni < 8; ++ni)
        bias_v[ni] = *(const float2*)(bias + warp_n * 64 + ni * 8 + 2 * lc);

    // ---- Fill W once per CTA (persistent): 12288 float4, 24 per thread.
    #pragma unroll
    for (int i = 0; i < 24; ++i) {
        int idx = tid + i * NTHREADS;
        int n  = idx / 48;
        int c4 = idx % 48;
        float4 v = *(const float4*)(W + (size_t)n * KTOT + c4 * 4);
        uint32_t* d = Bs + n * STRIDE + c4 * 2;
        d[0] = h2(v.x, v.y);
        d[1] = h2(v.z, v.w);
    }

    // ---- Prologue: fill A[0] for the first tile (group-local rows).
    int t0 = blockIdx.x;
    if (t0 < ntiles) {
        int e0 = t0 * BM;
        #pragma unroll
        for (int i = 0; i < 12; ++i) {
            int idx = gtid + i * 128;          // 0..1535 within group
            int r  = warp_m * 32 + idx / 48;   // group fills its own 32 rows
            int c4 = idx % 48;
            int e  = e0 + r; if (e >= M) e = M - 1;
            const float* p = (c4 < 32)
                ? (V + (size_t)__ldg(src0 + e) * ATOM + c4 * 4)
                : (E + (size_t)e * BOND + (c4 - 32) * 4);
            float4 v = *(const float4*)p;
            uint32_t* d = Abuf[0] + r * STRIDE + c4 * 2;
            d[0] = h2(v.x, v.y);
            d[1] = h2(v.z, v.w);
        }
    }
    __syncthreads();   // W + first A visible to everyone

    int cur = 0;
    for (int t = t0; t < ntiles; t += G) {
        const int e0  = t * BM;
        const int tn  = t + G;
        const bool hn = (tn < ntiles);
        const int e0n = tn * BM;
        const uint32_t* Ac = Abuf[cur];
        uint32_t* An = Abuf[cur ^ 1];

        float acc[2][8][4];
        #pragma unroll
        for (int mi = 0; mi < 2; ++mi)
            #pragma unroll
            for (int ni = 0; ni < 8; ++ni)
                #pragma unroll
                for (int c = 0; c < 4; ++c)
                    acc[mi][ni][c] = 0.f;

        // Rotated pipeline: LDG batch 0 up front; each block then does
        // [LDG batch b+1] -> [STS batch b] -> [4 MMA k-steps], so every
        // gather LDG gets >= one full MMA block of latency cover, and the
        // last STS stalls are buried before the final MMA block instead of
        // at the tile barrier.
        float4 g[4];
        int gr[4], gc[4];
        if (hn) {
            #pragma unroll
            for (int i = 0; i < 4; ++i) {
                int idx = gtid + i * 128;
                gr[i] = warp_m * 32 + idx / 48;
                gc[i] = idx % 48;
                int e = e0n + gr[i]; if (e >= M) e = M - 1;
                const float* p = (gc[i] < 32)
                    ? (V + (size_t)__ldg(src0 + e) * ATOM + gc[i] * 4)
                    : (E + (size_t)e * BOND + (gc[i] - 32) * 4);
                g[i] = *(const float4*)p;
            }
        }

        #pragma unroll
        for (int b = 0; b < 3; ++b) {
            // Next batch's LDGs first (independent of current g registers'
            // consumption order only through ptxas scheduling).
            float4 gn[4];
            int grn[4], gcn[4];
            if (hn && b < 2) {
                #pragma unroll
                for (int i = 0; i < 4; ++i) {
                    int idx = gtid + ((b + 1) * 4 + i) * 128;
                    grn[i] = warp_m * 32 + idx / 48;
                    gcn[i] = idx % 48;
                    int e = e0n + grn[i]; if (e >= M) e = M - 1;
                    const float* p = (gcn[i] < 32)
                        ? (V + (size_t)__ldg(src0 + e) * ATOM + gcn[i] * 4)
                        : (E + (size_t)e * BOND + (gcn[i] - 32) * 4);
                    gn[i] = *(const float4*)p;
                }
            }

            // STS current batch (LDGs issued one block earlier are long done).
            if (hn) {
                #pragma unroll
                for (int i = 0; i < 4; ++i) {
                    uint32_t* d = An + gr[i] * STRIDE + gc[i] * 2;
                    d[0] = h2(g[i].x, g[i].y);
                    d[1] = h2(g[i].z, g[i].w);
                }
            }

            // 4 MMA k-steps (unchanged from the champion).
            #pragma unroll
            for (int kk = b * 4; kk < b * 4 + 4; ++kk) {
                const int kb = kk * 8;
                uint32_t a[2][4], bf[8][2];
                #pragma unroll
                for (int mi = 0; mi < 2; ++mi) {
                    int r = warp_m * 32 + mi * 16 + lr;
                    const uint32_t* ap = Ac + r * STRIDE + kb;
                    a[mi][0] = ap[lc];
                    a[mi][1] = ap[8 * STRIDE + lc];
                    a[mi][2] = ap[lc + 4];
                    a[mi][3] = ap[8 * STRIDE + lc + 4];
                }
                #pragma unroll
                for (int ni = 0; ni < 8; ++ni) {
                    int n = warp_n * 64 + ni * 8 + lr;
                    const uint32_t* bp = Bs + n * STRIDE + kb;
                    bf[ni][0] = bp[lc];
                    bf[ni][1] = bp[lc + 4];
                }
                #pragma unroll
                for (int mi = 0; mi < 2; ++mi)
                    #pragma unroll
                    for (int ni = 0; ni < 8; ++ni) {
                        asm volatile(
                            "mma.sync.aligned.m16n8k16.row.col.f32.f16.f16.f32 "
                            "{%0,%1,%2,%3}, {%4,%5,%6,%7}, {%8,%9}, {%0,%1,%2,%3};\n"
                            : "+f"(acc[mi][ni][0]), "+f"(acc[mi][ni][1]),
                              "+f"(acc[mi][ni][2]), "+f"(acc[mi][ni][3])
                            : "r"(a[mi][0]), "r"(a[mi][1]),
                              "r"(a[mi][2]), "r"(a[mi][3]),
                              "r"(bf[ni][0]), "r"(bf[ni][1]));
                    }
            }

            // Rotate batches.
            if (hn && b < 2) {
                #pragma unroll
                for (int i = 0; i < 4; ++i) {
                    g[i] = gn[i]; gr[i] = grn[i]; gc[i] = gcn[i];
                }
            }
        }

        // STS of the final batch (loaded before the last MMA block).
        if (hn) {
            #pragma unroll
            for (int i = 0; i < 4; ++i) {
                uint32_t* d = An + gr[i] * STRIDE + gc[i] * 2;
                d[0] = h2(g[i].x, g[i].y);
                d[1] = h2(g[i].z, g[i].w);
            }
        }

        // ---- Direct epilogue: fire-and-forget float2 STGs (no smem).
        #pragma unroll
        for (int mi = 0; mi < 2; ++mi) {
            int row0 = e0 + warp_m * 32 + mi * 16 + lr;
            int row1 = row0 + 8;
            #pragma unroll
            for (int ni = 0; ni < 8; ++ni) {
                int col = warp_n * 64 + ni * 8 + 2 * lc;
                float2 bb = bias_v[ni];
                if (row0 < M) {
                    float2 o;
                    o.x = acc[mi][ni][0] + bb.x;
                    o.y = acc[mi][ni][1] + bb.y;
                    *(float2*)(out + (size_t)row0 * NOUT + col) = o;
                }
                if (row1 < M) {
                    float2 o;
                    o.x = acc[mi][ni][2] + bb.x;
                    o.y = acc[mi][ni][3] + bb.y;
                    *(float2*)(out + (size_t)row1 * NOUT + col) = o;
                }
            }
        }

        // Quarter-group barrier (rows [32*warp_m, +32) group-private).
        asm volatile("bar.sync %0, %1;" :: "r"(warp_m + 1), "r"(128) : "memory");
        cur ^= 1;
    }
}

} // namespace

extern "C" void kernel_launch(void* const* d_in, const int* in_sizes, int n_in,
                              void* d_out, int out_size)
{
    const float* V   = (const float*)d_in[0];
    const float* E   = (const float*)d_in[1];
    const int*   EI  = (const int*)d_in[2];   // int32 (JAX canonicalized), row 0 = src
    const float* W   = (const float*)d_in[3];
    const float* b   = (const float*)d_in[4];
    float*       out = (float*)d_out;

    const int M = in_sizes[1] / BOND;
    const int ntiles = (M + BM - 1) / BM;

    int sms = 148;
    cudaDeviceGetAttribute(&sms, cudaDevAttrMultiProcessorCount, 0);
    int grid = sms < ntiles ? sms : ntiles;

    cudaFuncSetAttribute(bond_msg_kernel,
                         cudaFuncAttributeMaxDynamicSharedMemorySize, SMEM_BYTES);
    bond_msg_kernel<<<grid, NTHREADS, SMEM_BYTES>>>(V, E, EI, W, b, out, M, ntiles);
}

// round 15
// speedup vs baseline: 1.2850x; 1.2850x over previous
#include <cuda_runtime.h>
#include <cuda_fp16.h>
#include <cstdint>

namespace {

constexpr int ATOM = 128;
constexpr int BOND = 64;
constexpr int KTOT = 192;      // 48 float4 per row
constexpr int NOUT = 256;
constexpr int BM   = 128;      // edges per tile
constexpr int NTHREADS = 512;
constexpr int STRIDE_A = 100;  // A row stride (words); %32=4 -> frag LDS.32 conflict-free
constexpr int STRIDE_B = 104;  // B row stride (words); %32=8 -> paired LDS.64 conflict-free

// B paired-k layout: within each 8-word k-group, original words (q, q+4)
// are stored adjacently at positions (2q, 2q+1). Fragment pair (lc, lc+4)
// -> one LDS.64 at group*8 + 2*lc. A keeps the plain layout (fill is the
// per-tile gather; its simple indexing is load-bearing -- R11 lesson).

// smem layout (4B words): B first, then two A buffers
constexpr int SM_B_W  = 0;                            // 256 x 104
constexpr int SM_A0_W = NOUT * STRIDE_B;              // 128 x 100
constexpr int SM_A1_W = SM_A0_W + BM * STRIDE_A;
constexpr int SMEM_BYTES = (SM_A1_W + BM * STRIDE_A) * 4;   // 208896

__device__ __forceinline__ uint32_t h2(float lo, float hi) {
    __half2 h = __floats2half2_rn(lo, hi);
    return *(uint32_t*)&h;
}

__global__ void __launch_bounds__(NTHREADS, 1)
bond_msg_kernel(const float* __restrict__ V,
                const float* __restrict__ E,
                const int* __restrict__ src0,      // edge_index row 0 (int32)
                const float* __restrict__ W,       // [NOUT, KTOT]
                const float* __restrict__ bias,    // [NOUT]
                float* __restrict__ out,           // [M, NOUT]
                int M, int ntiles)
{
    extern __shared__ uint32_t smem[];
    uint32_t* Bs = smem + SM_B_W;
    uint32_t* Abuf[2] = { smem + SM_A0_W, smem + SM_A1_W };

    const int tid  = threadIdx.x;
    const int lane = tid & 31;
    const int wid  = tid >> 5;
    const int warp_m = wid >> 2;   // 0..3 -> quarter-group; 32 A rows each
    const int warp_n = wid & 3;    // 0..3 (64 cols each)
    const int lr = lane >> 2;
    const int lc = lane & 3;
    const int gtid = tid & 127;    // tid within the 128-thread quarter-group
    const int G  = gridDim.x;

    // ---- Fill W once per CTA, paired-k layout: 12288 slots, 24 per thread.
    // Slot s of row n: g=s>>2, q=s&3 -> float cols (16g+2q, +1) and
    // (16g+2q+8, +1), stored adjacently at word 2s (= g*8 + 2q).
    // One-time cost; amortized over all tiles.
    #pragma unroll
    for (int i = 0; i < 24; ++i) {
        int idx = tid + i * NTHREADS;      // 0..12287
        int n = idx / 48, s = idx % 48;
        int g = s >> 2, q = s & 3;
        int f0 = 16 * g + 2 * q;
        const float* row = W + (size_t)n * KTOT;
        float2 u = *(const float2*)(row + f0);
        float2 v = *(const float2*)(row + f0 + 8);
        *(uint2*)(Bs + n * STRIDE_B + 2 * s) =
            make_uint2(h2(u.x, u.y), h2(v.x, v.y));
    }

    // ---- Prologue: fill A[0] for the first tile (group-local rows, plain layout).
    int t0 = blockIdx.x;
    if (t0 < ntiles) {
        int e0 = t0 * BM;
        #pragma unroll
        for (int i = 0; i < 12; ++i) {
            int idx = gtid + i * 128;          // 0..1535 within group
            int r  = warp_m * 32 + idx / 48;   // group fills its own 32 rows
            int c4 = idx % 48;
            int e  = e0 + r; if (e >= M) e = M - 1;
            const float* p = (c4 < 32)
                ? (V + (size_t)__ldg(src0 + e) * ATOM + c4 * 4)
                : (E + (size_t)e * BOND + (c4 - 32) * 4);
            float4 v = *(const float4*)p;
            uint32_t* d = Abuf[0] + r * STRIDE_A + c4 * 2;
            d[0] = h2(v.x, v.y);
            d[1] = h2(v.z, v.w);
        }
    }
    __syncthreads();   // W + first A visible to everyone

    int cur = 0;
    for (int t = t0; t < ntiles; t += G) {
        const int e0  = t * BM;
        const int tn  = t + G;
        const bool hn = (tn < ntiles);
        const int e0n = tn * BM;
        const uint32_t* Ac = Abuf[cur];
        uint32_t* An = Abuf[cur ^ 1];

        float acc[2][8][4];
        #pragma unroll
        for (int mi = 0; mi < 2; ++mi)
            #pragma unroll
            for (int ni = 0; ni < 8; ++ni)
                #pragma unroll
                for (int c = 0; c < 4; ++c)
                    acc[mi][ni][c] = 0.f;

        // 3 pipeline stages (champion structure): prefetch batch b
        // -> 4 MMA k-steps -> STS batch b
        #pragma unroll
        for (int b = 0; b < 3; ++b) {
            float4 g[4];
            int gr[4], gc[4];
            if (hn) {
                #pragma unroll
                for (int i = 0; i < 4; ++i) {
                    int idx = gtid + (b * 4 + i) * 128;   // 0..1535
                    gr[i] = warp_m * 32 + idx / 48;
                    gc[i] = idx % 48;
                    int e = e0n + gr[i]; if (e >= M) e = M - 1;
                    const float* p = (gc[i] < 32)
                        ? (V + (size_t)__ldg(src0 + e) * ATOM + gc[i] * 4)
                        : (E + (size_t)e * BOND + (gc[i] - 32) * 4);
                    g[i] = *(const float4*)p;
                }
            }

            #pragma unroll
            for (int kk = b * 4; kk < b * 4 + 4; ++kk) {
                const int kb = kk * 8;
                uint32_t a[2][4], bf[8][2];
                #pragma unroll
                for (int mi = 0; mi < 2; ++mi) {
                    int r = warp_m * 32 + mi * 16 + lr;
                    const uint32_t* ap = Ac + r * STRIDE_A + kb;
                    a[mi][0] = ap[lc];
                    a[mi][1] = ap[8 * STRIDE_A + lc];
                    a[mi][2] = ap[lc + 4];
                    a[mi][3] = ap[8 * STRIDE_A + lc + 4];
                }
                // Paired-k B: one LDS.64 per ni replaces two LDS.32.
                // bw.x = old bp[lc], bw.y = old bp[lc+4].
                #pragma unroll
                for (int ni = 0; ni < 8; ++ni) {
                    int n = warp_n * 64 + ni * 8 + lr;
                    uint2 bw = *(const uint2*)(Bs + n * STRIDE_B + kb + 2 * lc);
                    bf[ni][0] = bw.x;
                    bf[ni][1] = bw.y;
                }
                #pragma unroll
                for (int mi = 0; mi < 2; ++mi)
                    #pragma unroll
                    for (int ni = 0; ni < 8; ++ni) {
                        asm volatile(
                            "mma.sync.aligned.m16n8k16.row.col.f32.f16.f16.f32 "
                            "{%0,%1,%2,%3}, {%4,%5,%6,%7}, {%8,%9}, {%0,%1,%2,%3};\n"
                            : "+f"(acc[mi][ni][0]), "+f"(acc[mi][ni][1]),
                              "+f"(acc[mi][ni][2]), "+f"(acc[mi][ni][3])
                            : "r"(a[mi][0]), "r"(a[mi][1]),
                              "r"(a[mi][2]), "r"(a[mi][3]),
                              "r"(bf[ni][0]), "r"(bf[ni][1]));
                    }
            }

            if (hn) {
                #pragma unroll
                for (int i = 0; i < 4; ++i) {
                    uint32_t* d = An + gr[i] * STRIDE_A + gc[i] * 2;
                    d[0] = h2(g[i].x, g[i].y);
                    d[1] = h2(g[i].z, g[i].w);
                }
            }
        }

        // ---- Direct epilogue: fire-and-forget float2 STGs (no smem).
        #pragma unroll
        for (int mi = 0; mi < 2; ++mi) {
            int row0 = e0 + warp_m * 32 + mi * 16 + lr;
            int row1 = row0 + 8;
            #pragma unroll
            for (int ni = 0; ni < 8; ++ni) {
                int col = warp_n * 64 + ni * 8 + 2 * lc;
                float2 bb = *(const float2*)(bias + col);
                if (row0 < M) {
                    float2 o;
                    o.x = acc[mi][ni][0] + bb.x;
                    o.y = acc[mi][ni][1] + bb.y;
                    *(float2*)(out + (size_t)row0 * NOUT + col) = o;
                }
                if (row1 < M) {
                    float2 o;
                    o.x = acc[mi][ni][2] + bb.x;
                    o.y = acc[mi][ni][3] + bb.y;
                    *(float2*)(out + (size_t)row1 * NOUT + col) = o;
                }
            }
        }

        // Quarter-group barrier (rows [32*warp_m, +32) group-private).
        asm volatile("bar.sync %0, %1;" :: "r"(warp_m + 1), "r"(128) : "memory");
        cur ^= 1;
    }
}

} // namespace

extern "C" void kernel_launch(void* const* d_in, const int* in_sizes, int n_in,
                              void* d_out, int out_size)
{
    const float* V   = (const float*)d_in[0];
    const float* E   = (const float*)d_in[1];
    const int*   EI  = (const int*)d_in[2];   // int32 (JAX canonicalized), row 0 = src
    const float* W   = (const float*)d_in[3];
    const float* b   = (const float*)d_in[4];
    float*       out = (float*)d_out;

    const int M = in_sizes[1] / BOND;
    const int ntiles = (M + BM - 1) / BM;

    int sms = 148;
    cudaDeviceGetAttribute(&sms, cudaDevAttrMultiProcessorCount, 0);
    int grid = sms < ntiles ? sms : ntiles;

    cudaFuncSetAttribute(bond_msg_kernel,
                         cudaFuncAttributeMaxDynamicSharedMemorySize, SMEM_BYTES);
    bond_msg_kernel<<<grid, NTHREADS, SMEM_BYTES>>>(V, E, EI, W, b, out, M, ntiles);
}

// round 16
// speedup vs baseline: 1.3522x; 1.0523x over previous
#include <cuda_runtime.h>
#include <cuda_fp16.h>
#include <cstdint>

namespace {

constexpr int ATOM = 128;
constexpr int BOND = 64;
constexpr int KTOT = 192;      // 48 float4 per row
constexpr int NOUT = 256;
constexpr int BM   = 128;      // edges per tile
constexpr int NTHREADS = 512;
constexpr int STRIDE_A = 100;  // A row stride (words); %32=4 -> frag LDS.32 conflict-free
constexpr int STRIDE_B = 104;  // B row stride (words); %32=8 -> paired LDS.64 conflict-free

// B layout (both transformations are one-time, in the W fill):
//  1. paired-k within each 8-word k-group: original words (q, q+4) stored
//     adjacently at (2q, 2q+1)  -> one LDS.64 per fragment pair (R15 win).
//  2. row permutation: physical row p holds W row psi(p), where within each
//     64-row block psi(8i+l) = 16*(i>>1) + (i&1) + 2*l. The k-loop keeps the
//     champion's LINEAR row index; accumulator columns come out permuted so
//     that each thread owns 4 consecutive output columns -> STG.128 epilogue
//     (R13's effect without R13's per-k-step index ALU).

// smem layout (4B words): B first, then two A buffers
constexpr int SM_B_W  = 0;                            // 256 x 104
constexpr int SM_A0_W = NOUT * STRIDE_B;              // 128 x 100
constexpr int SM_A1_W = SM_A0_W + BM * STRIDE_A;
constexpr int SMEM_BYTES = (SM_A1_W + BM * STRIDE_A) * 4;   // 208896

__device__ __forceinline__ uint32_t h2(float lo, float hi) {
    __half2 h = __floats2half2_rn(lo, hi);
    return *(uint32_t*)&h;
}

__global__ void __launch_bounds__(NTHREADS, 1)
bond_msg_kernel(const float* __restrict__ V,
                const float* __restrict__ E,
                const int* __restrict__ src0,      // edge_index row 0 (int32)
                const float* __restrict__ W,       // [NOUT, KTOT]
                const float* __restrict__ bias,    // [NOUT]
                float* __restrict__ out,           // [M, NOUT]
                int M, int ntiles)
{
    extern __shared__ uint32_t smem[];
    uint32_t* Bs = smem + SM_B_W;
    uint32_t* Abuf[2] = { smem + SM_A0_W, smem + SM_A1_W };

    const int tid  = threadIdx.x;
    const int lane = tid & 31;
    const int wid  = tid >> 5;
    const int warp_m = wid >> 2;   // 0..3 -> quarter-group; 32 A rows each
    const int warp_n = wid & 3;    // 0..3 (64 cols each)
    const int lr = lane >> 2;
    const int lc = lane & 3;
    const int gtid = tid & 127;    // tid within the 128-thread quarter-group
    const int G  = gridDim.x;

    // ---- Fill W once per CTA: paired-k words + permuted row placement.
    // W row n goes to physical row (n & ~63) + pi(n & 63), where
    // pi(w) = 8*(2*(w>>4) + (w&1)) + ((w&15)>>1)  (inverse of psi).
    #pragma unroll
    for (int i = 0; i < 24; ++i) {
        int idx = tid + i * NTHREADS;      // 0..12287
        int n = idx / 48, s = idx % 48;
        int nl = n & 63;
        int pr = (n & 192) + ((2 * (nl >> 4) + (nl & 1)) << 3) + ((nl & 15) >> 1);
        int g = s >> 2, q = s & 3;
        int f0 = 16 * g + 2 * q;
        const float* row = W + (size_t)n * KTOT;
        float2 u = *(const float2*)(row + f0);
        float2 v = *(const float2*)(row + f0 + 8);
        *(uint2*)(Bs + pr * STRIDE_B + 2 * s) =
            make_uint2(h2(u.x, u.y), h2(v.x, v.y));
    }

    // ---- Prologue: fill A[0] for the first tile (group-local rows, plain layout).
    int t0 = blockIdx.x;
    if (t0 < ntiles) {
        int e0 = t0 * BM;
        #pragma unroll
        for (int i = 0; i < 12; ++i) {
            int idx = gtid + i * 128;          // 0..1535 within group
            int r  = warp_m * 32 + idx / 48;   // group fills its own 32 rows
            int c4 = idx % 48;
            int e  = e0 + r; if (e >= M) e = M - 1;
            const float* p = (c4 < 32)
                ? (V + (size_t)__ldg(src0 + e) * ATOM + c4 * 4)
                : (E + (size_t)e * BOND + (c4 - 32) * 4);
            float4 v = *(const float4*)p;
            uint32_t* d = Abuf[0] + r * STRIDE_A + c4 * 2;
            d[0] = h2(v.x, v.y);
            d[1] = h2(v.z, v.w);
        }
    }
    __syncthreads();   // W + first A visible to everyone

    int cur = 0;
    for (int t = t0; t < ntiles; t += G) {
        const int e0  = t * BM;
        const int tn  = t + G;
        const bool hn = (tn < ntiles);
        const int e0n = tn * BM;
        const uint32_t* Ac = Abuf[cur];
        uint32_t* An = Abuf[cur ^ 1];

        float acc[2][8][4];
        #pragma unroll
        for (int mi = 0; mi < 2; ++mi)
            #pragma unroll
            for (int ni = 0; ni < 8; ++ni)
                #pragma unroll
                for (int c = 0; c < 4; ++c)
                    acc[mi][ni][c] = 0.f;

        // 3 pipeline stages (champion structure): prefetch batch b
        // -> 4 MMA k-steps -> STS batch b
        #pragma unroll
        for (int b = 0; b < 3; ++b) {
            float4 g[4];
            int gr[4], gc[4];
            if (hn) {
                #pragma unroll
                for (int i = 0; i < 4; ++i) {
                    int idx = gtid + (b * 4 + i) * 128;   // 0..1535
                    gr[i] = warp_m * 32 + idx / 48;
                    gc[i] = idx % 48;
                    int e = e0n + gr[i]; if (e >= M) e = M - 1;
                    const float* p = (gc[i] < 32)
                        ? (V + (size_t)__ldg(src0 + e) * ATOM + gc[i] * 4)
                        : (E + (size_t)e * BOND + (gc[i] - 32) * 4);
                    g[i] = *(const float4*)p;
                }
            }

            #pragma unroll
            for (int kk = b * 4; kk < b * 4 + 4; ++kk) {
                const int kb = kk * 8;
                uint32_t a[2][4], bf[8][2];
                #pragma unroll
                for (int mi = 0; mi < 2; ++mi) {
                    int r = warp_m * 32 + mi * 16 + lr;
                    const uint32_t* ap = Ac + r * STRIDE_A + kb;
                    a[mi][0] = ap[lc];
                    a[mi][1] = ap[8 * STRIDE_A + lc];
                    a[mi][2] = ap[lc + 4];
                    a[mi][3] = ap[8 * STRIDE_A + lc + 4];
                }
                // Linear physical row index (identical to R15 champion).
                #pragma unroll
                for (int ni = 0; ni < 8; ++ni) {
                    int n = warp_n * 64 + ni * 8 + lr;
                    uint2 bw = *(const uint2*)(Bs + n * STRIDE_B + kb + 2 * lc);
                    bf[ni][0] = bw.x;
                    bf[ni][1] = bw.y;
                }
                #pragma unroll
                for (int mi = 0; mi < 2; ++mi)
                    #pragma unroll
                    for (int ni = 0; ni < 8; ++ni) {
                        asm volatile(
                            "mma.sync.aligned.m16n8k16.row.col.f32.f16.f16.f32 "
                            "{%0,%1,%2,%3}, {%4,%5,%6,%7}, {%8,%9}, {%0,%1,%2,%3};\n"
                            : "+f"(acc[mi][ni][0]), "+f"(acc[mi][ni][1]),
                              "+f"(acc[mi][ni][2]), "+f"(acc[mi][ni][3])
                            : "r"(a[mi][0]), "r"(a[mi][1]),
                              "r"(a[mi][2]), "r"(a[mi][3]),
                              "r"(bf[ni][0]), "r"(bf[ni][1]));
                    }
            }

            if (hn) {
                #pragma unroll
                for (int i = 0; i < 4; ++i) {
                    uint32_t* d = An + gr[i] * STRIDE_A + gc[i] * 2;
                    d[0] = h2(g[i].x, g[i].y);
                    d[1] = h2(g[i].z, g[i].w);
                }
            }
        }

        // ---- Direct epilogue, STG.128: with the stored row permutation,
        // acc pair (2j, 2j+1) owns output cols 16j + 4lc + {0,1,2,3}:
        // row0 quad = (acc[2j].c0, acc[2j+1].c0, acc[2j].c1, acc[2j+1].c1).
        #pragma unroll
        for (int mi = 0; mi < 2; ++mi) {
            int row0 = e0 + warp_m * 32 + mi * 16 + lr;
            int row1 = row0 + 8;
            #pragma unroll
            for (int j = 0; j < 4; ++j) {
                int col = warp_n * 64 + 16 * j + 4 * lc;
                float4 bb = *(const float4*)(bias + col);
                if (row0 < M) {
                    float4 o;
                    o.x = acc[mi][2*j    ][0] + bb.x;
                    o.y = acc[mi][2*j + 1][0] + bb.y;
                    o.z = acc[mi][2*j    ][1] + bb.z;
                    o.w = acc[mi][2*j + 1][1] + bb.w;
                    *(float4*)(out + (size_t)row0 * NOUT + col) = o;
                }
                if (row1 < M) {
                    float4 o;
                    o.x = acc[mi][2*j    ][2] + bb.x;
                    o.y = acc[mi][2*j + 1][2] + bb.y;
                    o.z = acc[mi][2*j    ][3] + bb.z;
                    o.w = acc[mi][2*j + 1][3] + bb.w;
                    *(float4*)(out + (size_t)row1 * NOUT + col) = o;
                }
            }
        }

        // Quarter-group barrier (rows [32*warp_m, +32) group-private).
        asm volatile("bar.sync %0, %1;" :: "r"(warp_m + 1), "r"(128) : "memory");
        cur ^= 1;
    }
}

} // namespace

extern "C" void kernel_launch(void* const* d_in, const int* in_sizes, int n_in,
                              void* d_out, int out_size)
{
    const float* V   = (const float*)d_in[0];
    const float* E   = (const float*)d_in[1];
    const int*   EI  = (const int*)d_in[2];   // int32 (JAX canonicalized), row 0 = src
    const float* W   = (const float*)d_in[3];
    const float* b   = (const float*)d_in[4];
    float*       out = (float*)d_out;

    const int M = in_sizes[1] / BOND;
    const int ntiles = (M + BM - 1) / BM;

    int sms = 148;
    cudaDeviceGetAttribute(&sms, cudaDevAttrMultiProcessorCount, 0);
    int grid = sms < ntiles ? sms : ntiles;

    cudaFuncSetAttribute(bond_msg_kernel,
                         cudaFuncAttributeMaxDynamicSharedMemorySize, SMEM_BYTES);
    bond_msg_kernel<<<grid, NTHREADS, SMEM_BYTES>>>(V, E, EI, W, b, out, M, ntiles);
}